// round 12
// baseline (speedup 1.0000x reference)
#include <cuda_runtime.h>
#include <cuda_bf16.h>

// GaussianRender: 64 tiles (8x8) of 64x64 px, K=256 depth-sorted gaussians.
// alpha = clip(op*prob,.01,.99): gaussians provably far from a 4-row band
// (per-axis Schur bound) contribute exactly alpha=0.01 to every band pixel;
// runs of far gaussians collapse to acc += q*T0*S1 - q^2*S2rel, T -= q*m.
//
// Kernel A (64 CTAs x 256): ONE gather per tile. Per-band near sets built in
// parallel via atomicOr bitmaps (depth order preserved by bit position); gap
// sums O(1) from 6 exclusive prefix scans; 8 warps emit 16 band streams.
// Kernel B (1024 CTAs x 128): branch-free packed-f32x2 render, 2 px/thread.

#define KG     256
#define WIMG   512
#define NBANDS 16
#define EU     16            // u64 per entry (128 B)
#define EMAXB  (KG + 1)
#define SENT   48            // render smem entry cache

typedef unsigned long long u64;
union F2U { float2 f; u64 u; };

__device__ __align__(16) u64 g_ent[64][NBANDS][EMAXB * EU];
__device__ int g_cnt[64][NBANDS];

__device__ __forceinline__ u64 pk(float a, float b) { F2U t; t.f = make_float2(a, b); return t.u; }
__device__ __forceinline__ u64 ffma2(u64 a, u64 b, u64 c) {
    u64 d; asm("fma.rn.f32x2 %0, %1, %2, %3;" : "=l"(d) : "l"(a), "l"(b), "l"(c)); return d;
}
__device__ __forceinline__ u64 fmul2(u64 a, u64 b) {
    u64 d; asm("mul.rn.f32x2 %0, %1, %2;" : "=l"(d) : "l"(a), "l"(b)); return d;
}
__device__ __forceinline__ u64 fadd2(u64 a, u64 b) {
    u64 d; asm("add.rn.f32x2 %0, %1, %2;" : "=l"(d) : "l"(a), "l"(b)); return d;
}
__device__ __forceinline__ float ex2f(float x) {
    float y; asm("ex2.approx.f32 %0, %1;" : "=f"(y) : "f"(x)); return y;
}
__device__ __forceinline__ float lg2f(float x) {
    float y; asm("lg2.approx.f32 %0, %1;" : "=f"(y) : "f"(x)); return y;
}
__device__ __forceinline__ float clampa(float a) { return fminf(fmaxf(a, 0.01f), 0.99f); }

#define T_FAR (-6.6438561897747395f - 0.01f)   // log2(0.01) - margin

// ===================== Kernel A: per-tile parallel stream build ============
__global__ __launch_bounds__(256)
void build_kernel(const float* __restrict__ mu,
                  const float* __restrict__ cov,
                  const float* __restrict__ opac,
                  const float* __restrict__ col,
                  const int*   __restrict__ tidx)
{
    // rec: [0]=-mx [1]=-my [2]=k1 [3]=k2 [4]=k3 [5]=lop [6]=cr [7]=cg [8]=cb
    __shared__ float rec[KG][9];
    __shared__ float E1r[KG + 1], E1g[KG + 1], E1b[KG + 1];
    __shared__ float E2r[KG + 1], E2g[KG + 1], E2b[KG + 1];
    __shared__ float wsum[6][8];
    __shared__ unsigned int bandmask[NBANDS][8];
    __shared__ short snears[NBANDS][KG];

    const int t    = blockIdx.x;     // tile 0..63
    const int tx   = t & 7;
    const int ty   = t >> 3;
    const int tid  = threadIdx.x;    // 0..255 = depth slot j
    const int lane = tid & 31;
    const int warp = tid >> 5;

    const float x0 = (float)(tx * 64) + 0.5f, x1 = x0 + 63.0f;
    const float ybase = (float)(ty * 64) + 0.5f;   // row 0 of tile

    // zero bitmaps
    if (tid < NBANDS * 8) ((unsigned int*)bandmask)[tid] = 0u;
    __syncthreads();

    // ---- phase 1: gather 1 gaussian/thread, params + per-band atomicOr ----
    float cr, cg, cb;
    {
        const int g = __ldg(tidx + t * KG + tid);
        const float4 cv = __ldg((const float4*)(cov + g * 4));
        const float2 m  = __ldg((const float2*)(mu + g * 2));
        const float op  = __ldg(opac + g);
        cr = __ldg(col + g * 3 + 0);
        cg = __ldg(col + g * 3 + 1);
        cb = __ldg(col + g * 3 + 2);

        const float det = fmaxf(fmaf(cv.x, cv.w, -cv.y * cv.z), 1e-6f);
        const float inv = 1.0f / det;
        const float e  = -0.7213475204444817f;   // -0.5 * log2(e)
        const float k1 = e * cv.w * inv;
        const float k2 = -e * (cv.y + cv.z) * inv;
        const float k3 = e * cv.x * inv;
        const float lop = lg2f(op);

        rec[tid][0] = -m.x;  rec[tid][1] = -m.y;
        rec[tid][2] = k1;    rec[tid][3] = k2;
        rec[tid][4] = k3;    rec[tid][5] = lop;
        rec[tid][6] = cr;    rec[tid][7] = cg;    rec[tid][8] = cb;

        // x part of the Schur bound (band-independent)
        const float dlo = x0 - m.x, dhi = x1 - m.x;
        const float mdx = fmaxf(fmaxf(dlo, -dhi), 0.0f);
        const float bxp = __fdividef(e * mdx * mdx, cv.x) + lop;

        if (bxp >= T_FAR) {                 // x-near: test 16 bands
            const unsigned int bit = 1u << (tid & 31);
            const int word = tid >> 5;
            #pragma unroll
            for (int b = 0; b < NBANDS; ++b) {
                const float yb0 = ybase + (float)(b * 4);
                const float yb1 = yb0 + 3.0f;
                const float elo = yb0 - m.y, ehi = yb1 - m.y;
                const float mdy = fmaxf(fmaxf(elo, -ehi), 0.0f);
                const float byp = __fdividef(e * mdy * mdy, cv.w) + lop;
                if (byp >= T_FAR)
                    atomicOr(&bandmask[b][word], bit);
            }
        }
    }

    // ---- phase 2: exclusive prefix sums of (c, j*c) ----
    {
        const float fj = (float)tid;
        float v[6] = { cr, cg, cb, fj * cr, fj * cg, fj * cb };
        float inc[6];
        #pragma unroll
        for (int q = 0; q < 6; ++q) {
            float x = v[q];
            #pragma unroll
            for (int o = 1; o < 32; o <<= 1) {
                const float n = __shfl_up_sync(0xffffffffu, x, o);
                if (lane >= o) x += n;
            }
            inc[q] = x;
            if (lane == 31) wsum[q][warp] = x;
        }
        __syncthreads();
        float off[6] = {0.f, 0.f, 0.f, 0.f, 0.f, 0.f};
        #pragma unroll
        for (int w = 0; w < 8; ++w) {
            if (w < warp) {
                #pragma unroll
                for (int q = 0; q < 6; ++q) off[q] += wsum[q][w];
            }
        }
        E1r[tid] = off[0] + inc[0] - v[0];
        E1g[tid] = off[1] + inc[1] - v[1];
        E1b[tid] = off[2] + inc[2] - v[2];
        E2r[tid] = off[3] + inc[3] - v[3];
        E2g[tid] = off[4] + inc[4] - v[4];
        E2b[tid] = off[5] + inc[5] - v[5];
        if (tid == KG - 1) {
            E1r[KG] = off[0] + inc[0];
            E1g[KG] = off[1] + inc[1];
            E1b[KG] = off[2] + inc[2];
            E2r[KG] = off[3] + inc[3];
            E2g[KG] = off[4] + inc[4];
            E2b[KG] = off[5] + inc[5];
        }
    }
    __syncthreads();

    // ---- phase 3: 8 warps emit 16 band streams in parallel ----
    const float q = 0.01f;
    for (int b = warp; b < NBANDS; b += 8) {
        const unsigned int m = (lane < 8) ? bandmask[b][lane] : 0u;
        int c = __popc(m);
        int incc = c;
        #pragma unroll
        for (int o = 1; o < 32; o <<= 1) {
            const int n = __shfl_up_sync(0xffffffffu, incc, o);
            if (lane >= o) incc += n;
        }
        const int off = incc - c;
        const int nn  = __shfl_sync(0xffffffffu, incc, 31);   // total nears

        // ordered near list (bit position == depth order)
        unsigned int mm = m;
        int r = 0;
        while (mm) {
            const int bit = __ffs(mm) - 1;
            snears[b][off + r] = (short)(lane * 32 + bit);
            ++r;
            mm &= mm - 1;
        }
        __syncwarp(0xffffffffu);

        // one lane per entry (nn+1 entries)
        for (int i = lane; i <= nn; i += 32) {
            const int start = (i == 0) ? 0 : (int)snears[b][i - 1] + 1;
            const int jend  = (i < nn) ? (int)snears[b][i] : KG;   // exclusive
            const float fs = (float)start;
            const float S1r = E1r[jend] - E1r[start];
            const float S1g = E1g[jend] - E1g[start];
            const float S1b = E1b[jend] - E1b[start];
            const float S2r = (E2r[jend] - E2r[start]) - fs * S1r;
            const float S2g = (E2g[jend] - E2g[start]) - fs * S1g;
            const float S2b = (E2b[jend] - E2b[start]) - fs * S1b;
            const float cm  = (float)(jend - start);
            u64* p = g_ent[t][b] + i * EU;
            p[0] = pk(q * S1r, q * S1r);
            p[1] = pk(q * S1g, q * S1g);
            p[2] = pk(q * S1b, q * S1b);
            p[3] = pk(-q * q * S2r, -q * q * S2r);
            p[4] = pk(-q * q * S2g, -q * q * S2g);
            p[5] = pk(-q * q * S2b, -q * q * S2b);
            p[6] = pk(-q * cm, -q * cm);
            if (i < nn) {
                const int j = snears[b][i];
                #pragma unroll
                for (int rr = 0; rr < 9; ++rr) { const float v = rec[j][rr]; p[7 + rr] = pk(v, v); }
            } else {
                #pragma unroll
                for (int rr = 7; rr < 16; ++rr) p[rr] = 0ull;   // dummy near
            }
        }
        if (lane == 0) g_cnt[t][b] = nn + 1;
    }
}

// ===================== Kernel B: branch-free band render ===================
#define ENT_BODY(P)                                                          \
    {                                                                        \
        const ulonglong2 v0 = (P)[0], v1 = (P)[1], v2 = (P)[2], v3 = (P)[3]; \
        const ulonglong2 v4 = (P)[4], v5 = (P)[5], v6 = (P)[6], v7 = (P)[7]; \
        aR = ffma2(tr, v0.x, aR);  aR = fadd2(aR, v1.y);                     \
        aG = ffma2(tr, v0.y, aG);  aG = fadd2(aG, v2.x);                     \
        aB = ffma2(tr, v1.x, aB);  aB = fadd2(aB, v2.y);                     \
        tr = fadd2(tr, v3.x);                                                \
        const u64 dx2 = fadd2(px2, v3.y);                                    \
        const u64 t0  = fmul2(v4.y, dx2);                                    \
        const u64 u2  = ffma2(t0, dx2, v6.x);                                \
        const u64 kx2 = fmul2(v5.x, dx2);                                    \
        const u64 dy2 = fadd2(py2, v4.x);                                    \
        const u64 q2  = ffma2(v5.y, dy2, kx2);                               \
        const u64 pw  = ffma2(dy2, q2, u2);                                  \
        F2U PW; PW.u = pw;                                                   \
        F2U al;                                                              \
        al.f.x = clampa(ex2f(PW.f.x));                                       \
        al.f.y = clampa(ex2f(PW.f.y));                                       \
        const u64 wv = fmul2(al.u, tr);                                      \
        tr = ffma2(al.u, m1, tr);                                            \
        aR = ffma2(wv, v6.y, aR);                                            \
        aG = ffma2(wv, v7.x, aG);                                            \
        aB = ffma2(wv, v7.y, aB);                                            \
    }

__global__ __launch_bounds__(128)
void render_kernel(float* __restrict__ out)
{
    __shared__ __align__(16) u64 sent[SENT * EU];   // 6 KB

    const int bid = blockIdx.x;
    const int t   = bid >> 4;        // tile
    const int b   = bid & 15;        // band (4 rows)
    const int tx  = t & 7;
    const int ty  = t >> 3;
    const int tid = threadIdx.x;

    const int cnt = g_cnt[t][b];
    const u64* gsrc = g_ent[t][b];
    const int ns = (cnt < SENT) ? cnt : SENT;
    {
        const ulonglong2* s2p = (const ulonglong2*)gsrc;
        ulonglong2* d2p = (ulonglong2*)sent;
        const int n2 = ns * (EU / 2);
        for (int i = tid; i < n2; i += 128) d2p[i] = s2p[i];
    }
    __syncthreads();

    // 2 px/thread: column lx, rows b*4 + h*2 + {0,1}
    const int lx = tid & 63;
    const int h  = tid >> 6;
    const float px = (float)(tx * 64 + lx) + 0.5f;
    const float py = (float)(ty * 64 + b * 4 + h * 2) + 0.5f;
    const u64 px2 = pk(px, px);
    const u64 py2 = pk(py, py + 1.0f);
    const u64 m1  = pk(-1.0f, -1.0f);

    u64 aR = 0, aG = 0, aB = 0;
    u64 tr = pk(1.0f, 1.0f);

    const ulonglong2* p = (const ulonglong2*)sent;
    for (int e = 0; e < ns; ++e, p += 8) ENT_BODY(p)
    if (cnt > SENT) {
        const ulonglong2* pg = (const ulonglong2*)(gsrc + SENT * EU);
        for (int e = SENT; e < cnt; ++e, pg += 8) ENT_BODY(pg)
    }

    // write 2 pixels
    const int gx = tx * 64 + lx;
    const int gy = ty * 64 + b * 4 + h * 2;
    F2U R, G, B; R.u = aR; G.u = aG; B.u = aB;
    float* o = out + ((size_t)gy * WIMG + gx) * 3;
    o[0] = R.f.x; o[1] = G.f.x; o[2] = B.f.x;
    o += WIMG * 3;
    o[0] = R.f.y; o[1] = G.f.y; o[2] = B.f.y;
}

extern "C" void kernel_launch(void* const* d_in, const int* in_sizes, int n_in,
                              void* d_out, int out_size)
{
    const float* mu   = (const float*)d_in[0];
    const float* cov  = (const float*)d_in[1];
    const float* opac = (const float*)d_in[2];
    const float* col  = (const float*)d_in[3];
    const int*   tidx = (const int*)  d_in[4];
    float* out = (float*)d_out;

    build_kernel<<<64, 256>>>(mu, cov, opac, col, tidx);
    render_kernel<<<1024, 128>>>(out);
}

// round 13
// speedup vs baseline: 1.2179x; 1.2179x over previous
#include <cuda_runtime.h>
#include <cuda_bf16.h>

// GaussianRender, single fused launch: 128 CTAs = 64 tiles x 2 halves,
// 512 threads. Each CTA: gather its tile's 256 gaussians once -> build 8
// per-band (4-row) run/near streams in smem (atomicOr bitmaps + prefix-scan
// gap sums + warp-per-band emit) -> all threads render 4 px from smem.
// alpha = clip(op*prob,.01,.99): band-far gaussians (per-axis Schur bound)
// contribute exactly alpha=0.01; far runs collapse to
//   acc += q*T0*S1 - q^2*S2rel,  T -= q*m   (pixel-independent sums).
// Per-band entry cap 24 with exact brute-force fallback (never taken here).

#define KG     256
#define WIMG   512
#define NB     8             // bands per CTA (4 rows each)
#define EU     16            // u64 per entry (128 B)
#define ECAP   24            // entries per band in smem

typedef unsigned long long u64;
union F2U { float2 f; u64 u; };

__device__ __forceinline__ u64 pk(float a, float b) { F2U t; t.f = make_float2(a, b); return t.u; }
__device__ __forceinline__ u64 ffma2(u64 a, u64 b, u64 c) {
    u64 d; asm("fma.rn.f32x2 %0, %1, %2, %3;" : "=l"(d) : "l"(a), "l"(b), "l"(c)); return d;
}
__device__ __forceinline__ u64 fmul2(u64 a, u64 b) {
    u64 d; asm("mul.rn.f32x2 %0, %1, %2;" : "=l"(d) : "l"(a), "l"(b)); return d;
}
__device__ __forceinline__ u64 fadd2(u64 a, u64 b) {
    u64 d; asm("add.rn.f32x2 %0, %1, %2;" : "=l"(d) : "l"(a), "l"(b)); return d;
}
__device__ __forceinline__ float ex2f(float x) {
    float y; asm("ex2.approx.f32 %0, %1;" : "=f"(y) : "f"(x)); return y;
}
__device__ __forceinline__ float lg2f(float x) {
    float y; asm("lg2.approx.f32 %0, %1;" : "=f"(y) : "f"(x)); return y;
}
__device__ __forceinline__ float clampa(float a) { return fminf(fmaxf(a, 0.01f), 0.99f); }

#define T_FAR (-6.6438561897747395f - 0.01f)   // log2(0.01) - margin

// entry as ulonglong2[8]:
//  v0={s1r,s1g} v1={s1b,s2r} v2={s2g,s2b} v3={scnt,-mx}
//  v4={-my,k1}  v5={k2,k3}   v6={lop,cr}  v7={cg,cb}
#define ENT_BODY(P)                                                          \
    {                                                                        \
        const ulonglong2 v0 = (P)[0], v1 = (P)[1], v2 = (P)[2], v3 = (P)[3]; \
        const ulonglong2 v4 = (P)[4], v5 = (P)[5], v6 = (P)[6], v7 = (P)[7]; \
        aR0 = ffma2(trA, v0.x, aR0);  aR0 = fadd2(aR0, v1.y);                \
        aG0 = ffma2(trA, v0.y, aG0);  aG0 = fadd2(aG0, v2.x);                \
        aB0 = ffma2(trA, v1.x, aB0);  aB0 = fadd2(aB0, v2.y);                \
        trA = fadd2(trA, v3.x);                                              \
        aR1 = ffma2(trB, v0.x, aR1);  aR1 = fadd2(aR1, v1.y);                \
        aG1 = ffma2(trB, v0.y, aG1);  aG1 = fadd2(aG1, v2.x);                \
        aB1 = ffma2(trB, v1.x, aB1);  aB1 = fadd2(aB1, v2.y);                \
        trB = fadd2(trB, v3.x);                                              \
        const u64 dx2 = fadd2(px2, v3.y);                                    \
        const u64 t0  = fmul2(v4.y, dx2);                                    \
        const u64 u2  = ffma2(t0, dx2, v6.x);                                \
        const u64 kx2 = fmul2(v5.x, dx2);                                    \
        const u64 dyA = fadd2(pyA, v4.x);                                    \
        const u64 qA  = ffma2(v5.y, dyA, kx2);                               \
        const u64 pwA = ffma2(dyA, qA, u2);                                  \
        const u64 dyB = fadd2(pyB, v4.x);                                    \
        const u64 qB  = ffma2(v5.y, dyB, kx2);                               \
        const u64 pwB = ffma2(dyB, qB, u2);                                  \
        F2U PA, PB; PA.u = pwA; PB.u = pwB;                                  \
        F2U alA, alB;                                                        \
        alA.f.x = clampa(ex2f(PA.f.x));                                      \
        alA.f.y = clampa(ex2f(PA.f.y));                                      \
        alB.f.x = clampa(ex2f(PB.f.x));                                      \
        alB.f.y = clampa(ex2f(PB.f.y));                                      \
        const u64 wvA = fmul2(alA.u, trA);                                   \
        trA = ffma2(alA.u, m1, trA);                                         \
        const u64 wvB = fmul2(alB.u, trB);                                   \
        trB = ffma2(alB.u, m1, trB);                                         \
        aR0 = ffma2(wvA, v6.y, aR0);                                         \
        aG0 = ffma2(wvA, v7.x, aG0);                                         \
        aB0 = ffma2(wvA, v7.y, aB0);                                         \
        aR1 = ffma2(wvB, v6.y, aR1);                                         \
        aG1 = ffma2(wvB, v7.x, aG1);                                         \
        aB1 = ffma2(wvB, v7.y, aB1);                                         \
    }

__global__ __launch_bounds__(512)
void fused_kernel(const float* __restrict__ mu,
                  const float* __restrict__ cov,
                  const float* __restrict__ opac,
                  const float* __restrict__ col,
                  const int*   __restrict__ tidx,
                  float*       __restrict__ out)
{
    // rec: [0]=-mx [1]=-my [2]=k1 [3]=k2 [4]=k3 [5]=lop [6]=cr [7]=cg [8]=cb
    __shared__ float rec[KG][9];                              // 9.2 KB
    __shared__ float E1r[KG + 1], E1g[KG + 1], E1b[KG + 1];   // 6.2 KB total
    __shared__ float E2r[KG + 1], E2g[KG + 1], E2b[KG + 1];
    __shared__ float wsum[6][8];
    __shared__ unsigned int bandmask[NB][8];                  // 256 B
    __shared__ unsigned char snears[NB][KG];                  // 2 KB
    __shared__ __align__(16) u64 ent[NB][ECAP * EU];          // 24 KB
    __shared__ int scnt[NB];
    __shared__ int sovf[NB];

    const int bid  = blockIdx.x;
    const int t    = bid >> 1;       // tile 0..63
    const int half = bid & 1;        // 0: rows 0..31, 1: rows 32..63
    const int tx   = t & 7;
    const int ty   = t >> 3;
    const int tid  = threadIdx.x;    // 0..511
    const int lane = tid & 31;
    const int warp = tid >> 5;

    const float x0 = (float)(tx * 64) + 0.5f, x1 = x0 + 63.0f;
    const float ybase = (float)(ty * 64 + half * 32) + 0.5f;   // first row of half

    // zero bitmaps + flags
    if (tid < NB * 8) ((unsigned int*)bandmask)[tid] = 0u;
    if (tid >= 64 && tid < 64 + NB) { scnt[tid - 64] = 0; sovf[tid - 64] = 0; }
    __syncthreads();

    // ---- phase 1 (threads 0..255): gather + classify + warp scans ----
    float cr = 0.f, cg = 0.f, cb = 0.f;
    if (tid < KG) {
        const int g = __ldg(tidx + t * KG + tid);
        const float4 cv = __ldg((const float4*)(cov + g * 4));
        const float2 m  = __ldg((const float2*)(mu + g * 2));
        const float op  = __ldg(opac + g);
        cr = __ldg(col + g * 3 + 0);
        cg = __ldg(col + g * 3 + 1);
        cb = __ldg(col + g * 3 + 2);

        const float det = fmaxf(fmaf(cv.x, cv.w, -cv.y * cv.z), 1e-6f);
        const float inv = 1.0f / det;
        const float e  = -0.7213475204444817f;   // -0.5 * log2(e)
        const float k1 = e * cv.w * inv;
        const float k2 = -e * (cv.y + cv.z) * inv;
        const float k3 = e * cv.x * inv;
        const float lop = lg2f(op);

        rec[tid][0] = -m.x;  rec[tid][1] = -m.y;
        rec[tid][2] = k1;    rec[tid][3] = k2;
        rec[tid][4] = k3;    rec[tid][5] = lop;
        rec[tid][6] = cr;    rec[tid][7] = cg;    rec[tid][8] = cb;

        // x-part of the Schur bound
        const float dlo = x0 - m.x, dhi = x1 - m.x;
        const float mdx = fmaxf(fmaxf(dlo, -dhi), 0.0f);
        const float bxp = __fdividef(e * mdx * mdx, cv.x) + lop;

        if (bxp >= T_FAR) {                // x-near: test the 8 local bands
            const unsigned int bit = 1u << lane;
            const int word = tid >> 5;
            #pragma unroll
            for (int b = 0; b < NB; ++b) {
                const float yb0 = ybase + (float)(b * 4);
                const float yb1 = yb0 + 3.0f;
                const float elo = yb0 - m.y, ehi = yb1 - m.y;
                const float mdy = fmaxf(fmaxf(elo, -ehi), 0.0f);
                const float byp = __fdividef(e * mdy * mdy, cv.w) + lop;
                if (byp >= T_FAR)
                    atomicOr(&bandmask[b][word], bit);
            }
        }

        // warp-level inclusive scans of (c, j*c)
        const float fj = (float)tid;
        float v[6] = { cr, cg, cb, fj * cr, fj * cg, fj * cb };
        #pragma unroll
        for (int q = 0; q < 6; ++q) {
            float x = v[q];
            #pragma unroll
            for (int o = 1; o < 32; o <<= 1) {
                const float n = __shfl_up_sync(0xffffffffu, x, o);
                if (lane >= o) x += n;
            }
            // stash inclusive scan in E arrays temporarily
            if (q == 0) E1r[tid] = x;
            else if (q == 1) E1g[tid] = x;
            else if (q == 2) E1b[tid] = x;
            else if (q == 3) E2r[tid] = x;
            else if (q == 4) E2g[tid] = x;
            else             E2b[tid] = x;
            if (lane == 31) wsum[q][warp] = x;
        }
    }
    __syncthreads();

    // ---- phase 2 (threads 0..255): finalize exclusive prefix sums ----
    if (tid < KG) {
        float off[6] = {0.f, 0.f, 0.f, 0.f, 0.f, 0.f};
        #pragma unroll
        for (int w = 0; w < 8; ++w) {
            if (w < warp) {
                #pragma unroll
                for (int q = 0; q < 6; ++q) off[q] += wsum[q][w];
            }
        }
        const float fj = (float)tid;
        E1r[tid] = E1r[tid] + off[0] - cr;
        E1g[tid] = E1g[tid] + off[1] - cg;
        E1b[tid] = E1b[tid] + off[2] - cb;
        E2r[tid] = E2r[tid] + off[3] - fj * cr;
        E2g[tid] = E2g[tid] + off[4] - fj * cg;
        E2b[tid] = E2b[tid] + off[5] - fj * cb;
        if (tid == KG - 1) {
            E1r[KG] = E1r[KG - 1] + cr;
            E1g[KG] = E1g[KG - 1] + cg;
            E1b[KG] = E1b[KG - 1] + cb;
            E2r[KG] = E2r[KG - 1] + fj * cr;
            E2g[KG] = E2g[KG - 1] + fj * cg;
            E2b[KG] = E2b[KG - 1] + fj * cb;
        }
    }
    __syncthreads();

    // ---- phase 3 (warps 0..7): emit one band stream per warp ----
    if (warp < NB) {
        const int b = warp;
        const unsigned int m = (lane < 8) ? bandmask[b][lane] : 0u;
        int c = __popc(m);
        int incc = c;
        #pragma unroll
        for (int o = 1; o < 32; o <<= 1) {
            const int n = __shfl_up_sync(0xffffffffu, incc, o);
            if (lane >= o) incc += n;
        }
        const int off = incc - c;
        const int nn  = __shfl_sync(0xffffffffu, incc, 31);   // total nears

        unsigned int mm = m;
        int r = 0;
        while (mm) {
            const int bit = __ffs(mm) - 1;
            snears[b][off + r] = (unsigned char)(lane * 32 + bit);
            ++r;
            mm &= mm - 1;
        }
        __syncwarp(0xffffffffu);

        if (nn + 1 <= ECAP) {
            const float q = 0.01f;
            for (int i = lane; i <= nn; i += 32) {
                const int start = (i == 0) ? 0 : (int)snears[b][i - 1] + 1;
                const int jend  = (i < nn) ? (int)snears[b][i] : KG;  // exclusive
                const float fs = (float)start;
                const float S1r = E1r[jend] - E1r[start];
                const float S1g = E1g[jend] - E1g[start];
                const float S1b = E1b[jend] - E1b[start];
                const float S2r = (E2r[jend] - E2r[start]) - fs * S1r;
                const float S2g = (E2g[jend] - E2g[start]) - fs * S1g;
                const float S2b = (E2b[jend] - E2b[start]) - fs * S1b;
                const float cm  = (float)(jend - start);
                u64* p = ent[b] + i * EU;
                p[0] = pk(q * S1r, q * S1r);
                p[1] = pk(q * S1g, q * S1g);
                p[2] = pk(q * S1b, q * S1b);
                p[3] = pk(-q * q * S2r, -q * q * S2r);
                p[4] = pk(-q * q * S2g, -q * q * S2g);
                p[5] = pk(-q * q * S2b, -q * q * S2b);
                p[6] = pk(-q * cm, -q * cm);
                if (i < nn) {
                    const int j = snears[b][i];
                    #pragma unroll
                    for (int rr = 0; rr < 9; ++rr) { const float v = rec[j][rr]; p[7 + rr] = pk(v, v); }
                } else {
                    #pragma unroll
                    for (int rr = 7; rr < 16; ++rr) p[rr] = 0ull;   // dummy near
                }
            }
            if (lane == 0) { scnt[b] = nn + 1; sovf[b] = 0; }
        } else {
            if (lane == 0) { scnt[b] = 0; sovf[b] = 1; }
        }
    }
    __syncthreads();

    // ---- phase 4: render 4 px/thread ----
    const int lx = tid & 63;
    const int bl = tid >> 6;                     // local band 0..7
    const float px  = (float)(tx * 64 + lx) + 0.5f;
    const float py0 = ybase + (float)(bl * 4);
    const u64 px2 = pk(px, px);
    const u64 pyA = pk(py0, py0 + 1.0f);
    const u64 pyB = pk(py0 + 2.0f, py0 + 3.0f);
    const u64 m1  = pk(-1.0f, -1.0f);

    u64 aR0 = 0, aG0 = 0, aB0 = 0, aR1 = 0, aG1 = 0, aB1 = 0;
    u64 trA = pk(1.0f, 1.0f), trB = pk(1.0f, 1.0f);

    if (!sovf[bl]) {
        const int cnt = scnt[bl];
        const ulonglong2* p = (const ulonglong2*)ent[bl];
        for (int e = 0; e < cnt; ++e, p += 8) ENT_BODY(p)
    } else {
        // exact brute force from rec (never taken on this input)
        for (int k = 0; k < KG; ++k) {
            const u64 nmx = pk(rec[k][0], rec[k][0]);
            const u64 nmy = pk(rec[k][1], rec[k][1]);
            const u64 k1  = pk(rec[k][2], rec[k][2]);
            const u64 k2  = pk(rec[k][3], rec[k][3]);
            const u64 k3  = pk(rec[k][4], rec[k][4]);
            const u64 lop = pk(rec[k][5], rec[k][5]);
            const u64 crr = pk(rec[k][6], rec[k][6]);
            const u64 cgg = pk(rec[k][7], rec[k][7]);
            const u64 cbb = pk(rec[k][8], rec[k][8]);
            const u64 dx2 = fadd2(px2, nmx);
            const u64 t0  = fmul2(k1, dx2);
            const u64 u2  = ffma2(t0, dx2, lop);
            const u64 kx2 = fmul2(k2, dx2);
            const u64 dyA = fadd2(pyA, nmy);
            const u64 qA  = ffma2(k3, dyA, kx2);
            const u64 pwA = ffma2(dyA, qA, u2);
            const u64 dyB = fadd2(pyB, nmy);
            const u64 qB  = ffma2(k3, dyB, kx2);
            const u64 pwB = ffma2(dyB, qB, u2);
            F2U PA, PB; PA.u = pwA; PB.u = pwB;
            F2U alA, alB;
            alA.f.x = clampa(ex2f(PA.f.x));
            alA.f.y = clampa(ex2f(PA.f.y));
            alB.f.x = clampa(ex2f(PB.f.x));
            alB.f.y = clampa(ex2f(PB.f.y));
            const u64 wvA = fmul2(alA.u, trA);
            trA = ffma2(alA.u, m1, trA);
            const u64 wvB = fmul2(alB.u, trB);
            trB = ffma2(alB.u, m1, trB);
            aR0 = ffma2(wvA, crr, aR0);
            aG0 = ffma2(wvA, cgg, aG0);
            aB0 = ffma2(wvA, cbb, aB0);
            aR1 = ffma2(wvB, crr, aR1);
            aG1 = ffma2(wvB, cgg, aG1);
            aB1 = ffma2(wvB, cbb, aB1);
        }
    }

    // ---- epilogue: write 4 pixels ----
    const int gx = tx * 64 + lx;
    const int gy = ty * 64 + half * 32 + bl * 4;
    F2U R0, G0, B0, R1, G1, B1;
    R0.u = aR0; G0.u = aG0; B0.u = aB0;
    R1.u = aR1; G1.u = aG1; B1.u = aB1;
    float* o = out + ((size_t)gy * WIMG + gx) * 3;
    o[0] = R0.f.x; o[1] = G0.f.x; o[2] = B0.f.x;  o += WIMG * 3;
    o[0] = R0.f.y; o[1] = G0.f.y; o[2] = B0.f.y;  o += WIMG * 3;
    o[0] = R1.f.x; o[1] = G1.f.x; o[2] = B1.f.x;  o += WIMG * 3;
    o[0] = R1.f.y; o[1] = G1.f.y; o[2] = B1.f.y;
}

extern "C" void kernel_launch(void* const* d_in, const int* in_sizes, int n_in,
                              void* d_out, int out_size)
{
    const float* mu   = (const float*)d_in[0];
    const float* cov  = (const float*)d_in[1];
    const float* opac = (const float*)d_in[2];
    const float* col  = (const float*)d_in[3];
    const int*   tidx = (const int*)  d_in[4];
    float* out = (float*)d_out;

    // 64 tiles x 2 halves = 128 CTAs, 512 threads, single launch
    fused_kernel<<<128, 512>>>(mu, cov, opac, col, tidx, out);
}

// round 14
// speedup vs baseline: 1.2216x; 1.0030x over previous
#include <cuda_runtime.h>
#include <cuda_bf16.h>

// GaussianRender, single fused launch: 256 CTAs = 64 tiles x 4 quarters
// (16 rows), 256 threads. Each CTA: gather its tile's 256 gaussians ->
// build 4 per-band (4-row) run/near streams in smem (atomicOr bitmaps +
// prefix-scan gap sums + warp-per-band emit) -> render 4 px/thread.
// alpha = clip(op*prob,.01,.99): band-far gaussians (per-axis Schur bound)
// contribute exactly alpha=0.01; far runs collapse to
//   acc += q*T0*S1 - q^2*S2rel,  T -= q*m   (pixel-independent sums).
// ~29KB smem + 256 thr -> 2-3 CTAs/SM so phase latencies overlap across CTAs.

#define KG     256
#define WIMG   512
#define NB     4             // bands per CTA (4 rows each)
#define EU     16            // u64 per entry (128 B)
#define ECAP   24            // entries per band in smem

typedef unsigned long long u64;
union F2U { float2 f; u64 u; };

__device__ __forceinline__ u64 pk(float a, float b) { F2U t; t.f = make_float2(a, b); return t.u; }
__device__ __forceinline__ u64 ffma2(u64 a, u64 b, u64 c) {
    u64 d; asm("fma.rn.f32x2 %0, %1, %2, %3;" : "=l"(d) : "l"(a), "l"(b), "l"(c)); return d;
}
__device__ __forceinline__ u64 fmul2(u64 a, u64 b) {
    u64 d; asm("mul.rn.f32x2 %0, %1, %2;" : "=l"(d) : "l"(a), "l"(b)); return d;
}
__device__ __forceinline__ u64 fadd2(u64 a, u64 b) {
    u64 d; asm("add.rn.f32x2 %0, %1, %2;" : "=l"(d) : "l"(a), "l"(b)); return d;
}
__device__ __forceinline__ float ex2f(float x) {
    float y; asm("ex2.approx.f32 %0, %1;" : "=f"(y) : "f"(x)); return y;
}
__device__ __forceinline__ float lg2f(float x) {
    float y; asm("lg2.approx.f32 %0, %1;" : "=f"(y) : "f"(x)); return y;
}
__device__ __forceinline__ float clampa(float a) { return fminf(fmaxf(a, 0.01f), 0.99f); }

#define T_FAR (-6.6438561897747395f - 0.01f)   // log2(0.01) - margin

// entry as ulonglong2[8]:
//  v0={s1r,s1g} v1={s1b,s2r} v2={s2g,s2b} v3={scnt,-mx}
//  v4={-my,k1}  v5={k2,k3}   v6={lop,cr}  v7={cg,cb}
#define ENT_BODY(P)                                                          \
    {                                                                        \
        const ulonglong2 v0 = (P)[0], v1 = (P)[1], v2 = (P)[2], v3 = (P)[3]; \
        const ulonglong2 v4 = (P)[4], v5 = (P)[5], v6 = (P)[6], v7 = (P)[7]; \
        aR0 = ffma2(trA, v0.x, aR0);  aR0 = fadd2(aR0, v1.y);                \
        aG0 = ffma2(trA, v0.y, aG0);  aG0 = fadd2(aG0, v2.x);                \
        aB0 = ffma2(trA, v1.x, aB0);  aB0 = fadd2(aB0, v2.y);                \
        trA = fadd2(trA, v3.x);                                              \
        aR1 = ffma2(trB, v0.x, aR1);  aR1 = fadd2(aR1, v1.y);                \
        aG1 = ffma2(trB, v0.y, aG1);  aG1 = fadd2(aG1, v2.x);                \
        aB1 = ffma2(trB, v1.x, aB1);  aB1 = fadd2(aB1, v2.y);                \
        trB = fadd2(trB, v3.x);                                              \
        const u64 dx2 = fadd2(px2, v3.y);                                    \
        const u64 t0  = fmul2(v4.y, dx2);                                    \
        const u64 u2  = ffma2(t0, dx2, v6.x);                                \
        const u64 kx2 = fmul2(v5.x, dx2);                                    \
        const u64 dyA = fadd2(pyA, v4.x);                                    \
        const u64 qA  = ffma2(v5.y, dyA, kx2);                               \
        const u64 pwA = ffma2(dyA, qA, u2);                                  \
        const u64 dyB = fadd2(pyB, v4.x);                                    \
        const u64 qB  = ffma2(v5.y, dyB, kx2);                               \
        const u64 pwB = ffma2(dyB, qB, u2);                                  \
        F2U PA, PB; PA.u = pwA; PB.u = pwB;                                  \
        F2U alA, alB;                                                        \
        alA.f.x = clampa(ex2f(PA.f.x));                                      \
        alA.f.y = clampa(ex2f(PA.f.y));                                      \
        alB.f.x = clampa(ex2f(PB.f.x));                                      \
        alB.f.y = clampa(ex2f(PB.f.y));                                      \
        const u64 wvA = fmul2(alA.u, trA);                                   \
        trA = ffma2(alA.u, m1, trA);                                         \
        const u64 wvB = fmul2(alB.u, trB);                                   \
        trB = ffma2(alB.u, m1, trB);                                         \
        aR0 = ffma2(wvA, v6.y, aR0);                                         \
        aG0 = ffma2(wvA, v7.x, aG0);                                         \
        aB0 = ffma2(wvA, v7.y, aB0);                                         \
        aR1 = ffma2(wvB, v6.y, aR1);                                         \
        aG1 = ffma2(wvB, v7.x, aG1);                                         \
        aB1 = ffma2(wvB, v7.y, aB1);                                         \
    }

__global__ __launch_bounds__(256, 3)
void fused_kernel(const float* __restrict__ mu,
                  const float* __restrict__ cov,
                  const float* __restrict__ opac,
                  const float* __restrict__ col,
                  const int*   __restrict__ tidx,
                  float*       __restrict__ out)
{
    // rec: [0]=-mx [1]=-my [2]=k1 [3]=k2 [4]=k3 [5]=lop [6]=cr [7]=cg [8]=cb
    __shared__ float rec[KG][9];                              // 9.2 KB
    __shared__ float E1r[KG + 1], E1g[KG + 1], E1b[KG + 1];   // 6.2 KB total
    __shared__ float E2r[KG + 1], E2g[KG + 1], E2b[KG + 1];
    __shared__ float wsum[6][8];
    __shared__ unsigned int bandmask[NB][8];                  // 128 B
    __shared__ unsigned char snears[NB][KG];                  // 1 KB
    __shared__ __align__(16) u64 ent[NB][ECAP * EU];          // 12.3 KB
    __shared__ int scnt[NB];
    __shared__ int sovf[NB];

    const int bid  = blockIdx.x;
    const int t    = bid >> 2;       // tile 0..63
    const int qtr  = bid & 3;        // quarter: rows qtr*16 .. qtr*16+15
    const int tx   = t & 7;
    const int ty   = t >> 3;
    const int tid  = threadIdx.x;    // 0..255 = depth slot j
    const int lane = tid & 31;
    const int warp = tid >> 5;

    const float x0 = (float)(tx * 64) + 0.5f, x1 = x0 + 63.0f;
    const float ybase = (float)(ty * 64 + qtr * 16) + 0.5f;   // first row of quarter

    // zero bitmaps + flags
    if (tid < NB * 8) ((unsigned int*)bandmask)[tid] = 0u;
    if (tid >= 32 && tid < 32 + NB) { scnt[tid - 32] = 0; sovf[tid - 32] = 0; }
    __syncthreads();

    // ---- phase 1: gather 1 gaussian/thread + classify + warp scans ----
    float cr, cg, cb;
    {
        const int g = __ldg(tidx + t * KG + tid);
        const float4 cv = __ldg((const float4*)(cov + g * 4));
        const float2 m  = __ldg((const float2*)(mu + g * 2));
        const float op  = __ldg(opac + g);
        cr = __ldg(col + g * 3 + 0);
        cg = __ldg(col + g * 3 + 1);
        cb = __ldg(col + g * 3 + 2);

        const float det = fmaxf(fmaf(cv.x, cv.w, -cv.y * cv.z), 1e-6f);
        const float inv = 1.0f / det;
        const float e  = -0.7213475204444817f;   // -0.5 * log2(e)
        const float k1 = e * cv.w * inv;
        const float k2 = -e * (cv.y + cv.z) * inv;
        const float k3 = e * cv.x * inv;
        const float lop = lg2f(op);

        rec[tid][0] = -m.x;  rec[tid][1] = -m.y;
        rec[tid][2] = k1;    rec[tid][3] = k2;
        rec[tid][4] = k3;    rec[tid][5] = lop;
        rec[tid][6] = cr;    rec[tid][7] = cg;    rec[tid][8] = cb;

        // x-part of the Schur bound
        const float dlo = x0 - m.x, dhi = x1 - m.x;
        const float mdx = fmaxf(fmaxf(dlo, -dhi), 0.0f);
        const float bxp = __fdividef(e * mdx * mdx, cv.x) + lop;

        if (bxp >= T_FAR) {                // x-near: test the 4 local bands
            const unsigned int bit = 1u << lane;
            const int word = tid >> 5;
            #pragma unroll
            for (int b = 0; b < NB; ++b) {
                const float yb0 = ybase + (float)(b * 4);
                const float yb1 = yb0 + 3.0f;
                const float elo = yb0 - m.y, ehi = yb1 - m.y;
                const float mdy = fmaxf(fmaxf(elo, -ehi), 0.0f);
                const float byp = __fdividef(e * mdy * mdy, cv.w) + lop;
                if (byp >= T_FAR)
                    atomicOr(&bandmask[b][word], bit);
            }
        }

        // warp-level inclusive scans of (c, j*c)
        const float fj = (float)tid;
        float v[6] = { cr, cg, cb, fj * cr, fj * cg, fj * cb };
        #pragma unroll
        for (int q = 0; q < 6; ++q) {
            float x = v[q];
            #pragma unroll
            for (int o = 1; o < 32; o <<= 1) {
                const float n = __shfl_up_sync(0xffffffffu, x, o);
                if (lane >= o) x += n;
            }
            if (q == 0) E1r[tid] = x;
            else if (q == 1) E1g[tid] = x;
            else if (q == 2) E1b[tid] = x;
            else if (q == 3) E2r[tid] = x;
            else if (q == 4) E2g[tid] = x;
            else             E2b[tid] = x;
            if (lane == 31) wsum[q][warp] = x;
        }
    }
    __syncthreads();

    // ---- phase 2: finalize exclusive prefix sums ----
    {
        float off[6] = {0.f, 0.f, 0.f, 0.f, 0.f, 0.f};
        #pragma unroll
        for (int w = 0; w < 8; ++w) {
            if (w < warp) {
                #pragma unroll
                for (int q = 0; q < 6; ++q) off[q] += wsum[q][w];
            }
        }
        const float fj = (float)tid;
        E1r[tid] = E1r[tid] + off[0] - cr;
        E1g[tid] = E1g[tid] + off[1] - cg;
        E1b[tid] = E1b[tid] + off[2] - cb;
        E2r[tid] = E2r[tid] + off[3] - fj * cr;
        E2g[tid] = E2g[tid] + off[4] - fj * cg;
        E2b[tid] = E2b[tid] + off[5] - fj * cb;
        if (tid == KG - 1) {
            E1r[KG] = E1r[KG - 1] + cr;
            E1g[KG] = E1g[KG - 1] + cg;
            E1b[KG] = E1b[KG - 1] + cb;
            E2r[KG] = E2r[KG - 1] + fj * cr;
            E2g[KG] = E2g[KG - 1] + fj * cg;
            E2b[KG] = E2b[KG - 1] + fj * cb;
        }
    }
    __syncthreads();

    // ---- phase 3 (warps 0..3): emit one band stream per warp ----
    if (warp < NB) {
        const int b = warp;
        const unsigned int m = (lane < 8) ? bandmask[b][lane] : 0u;
        int c = __popc(m);
        int incc = c;
        #pragma unroll
        for (int o = 1; o < 32; o <<= 1) {
            const int n = __shfl_up_sync(0xffffffffu, incc, o);
            if (lane >= o) incc += n;
        }
        const int off = incc - c;
        const int nn  = __shfl_sync(0xffffffffu, incc, 31);   // total nears

        unsigned int mm = m;
        int r = 0;
        while (mm) {
            const int bit = __ffs(mm) - 1;
            snears[b][off + r] = (unsigned char)(lane * 32 + bit);
            ++r;
            mm &= mm - 1;
        }
        __syncwarp(0xffffffffu);

        if (nn + 1 <= ECAP) {
            const float q = 0.01f;
            for (int i = lane; i <= nn; i += 32) {
                const int start = (i == 0) ? 0 : (int)snears[b][i - 1] + 1;
                const int jend  = (i < nn) ? (int)snears[b][i] : KG;  // exclusive
                const float fs = (float)start;
                const float S1r = E1r[jend] - E1r[start];
                const float S1g = E1g[jend] - E1g[start];
                const float S1b = E1b[jend] - E1b[start];
                const float S2r = (E2r[jend] - E2r[start]) - fs * S1r;
                const float S2g = (E2g[jend] - E2g[start]) - fs * S1g;
                const float S2b = (E2b[jend] - E2b[start]) - fs * S1b;
                const float cm  = (float)(jend - start);
                u64* p = ent[b] + i * EU;
                p[0] = pk(q * S1r, q * S1r);
                p[1] = pk(q * S1g, q * S1g);
                p[2] = pk(q * S1b, q * S1b);
                p[3] = pk(-q * q * S2r, -q * q * S2r);
                p[4] = pk(-q * q * S2g, -q * q * S2g);
                p[5] = pk(-q * q * S2b, -q * q * S2b);
                p[6] = pk(-q * cm, -q * cm);
                if (i < nn) {
                    const int j = snears[b][i];
                    #pragma unroll
                    for (int rr = 0; rr < 9; ++rr) { const float v = rec[j][rr]; p[7 + rr] = pk(v, v); }
                } else {
                    #pragma unroll
                    for (int rr = 7; rr < 16; ++rr) p[rr] = 0ull;   // dummy near
                }
            }
            if (lane == 0) scnt[b] = nn + 1;
        } else {
            if (lane == 0) { scnt[b] = 0; sovf[b] = 1; }
        }
    }
    __syncthreads();

    // ---- phase 4: render 4 px/thread ----
    const int lx = tid & 63;
    const int bl = tid >> 6;                     // local band 0..3
    const float px  = (float)(tx * 64 + lx) + 0.5f;
    const float py0 = ybase + (float)(bl * 4);
    const u64 px2 = pk(px, px);
    const u64 pyA = pk(py0, py0 + 1.0f);
    const u64 pyB = pk(py0 + 2.0f, py0 + 3.0f);
    const u64 m1  = pk(-1.0f, -1.0f);

    u64 aR0 = 0, aG0 = 0, aB0 = 0, aR1 = 0, aG1 = 0, aB1 = 0;
    u64 trA = pk(1.0f, 1.0f), trB = pk(1.0f, 1.0f);

    if (!sovf[bl]) {
        const int cnt = scnt[bl];
        const ulonglong2* p = (const ulonglong2*)ent[bl];
        for (int e = 0; e < cnt; ++e, p += 8) ENT_BODY(p)
    } else {
        // exact brute force from rec (never taken on this input)
        for (int k = 0; k < KG; ++k) {
            const u64 nmx = pk(rec[k][0], rec[k][0]);
            const u64 nmy = pk(rec[k][1], rec[k][1]);
            const u64 kk1 = pk(rec[k][2], rec[k][2]);
            const u64 kk2 = pk(rec[k][3], rec[k][3]);
            const u64 kk3 = pk(rec[k][4], rec[k][4]);
            const u64 lop = pk(rec[k][5], rec[k][5]);
            const u64 crr = pk(rec[k][6], rec[k][6]);
            const u64 cgg = pk(rec[k][7], rec[k][7]);
            const u64 cbb = pk(rec[k][8], rec[k][8]);
            const u64 dx2 = fadd2(px2, nmx);
            const u64 t0  = fmul2(kk1, dx2);
            const u64 u2  = ffma2(t0, dx2, lop);
            const u64 kx2 = fmul2(kk2, dx2);
            const u64 dyA = fadd2(pyA, nmy);
            const u64 qA  = ffma2(kk3, dyA, kx2);
            const u64 pwA = ffma2(dyA, qA, u2);
            const u64 dyB = fadd2(pyB, nmy);
            const u64 qB  = ffma2(kk3, dyB, kx2);
            const u64 pwB = ffma2(dyB, qB, u2);
            F2U PA, PB; PA.u = pwA; PB.u = pwB;
            F2U alA, alB;
            alA.f.x = clampa(ex2f(PA.f.x));
            alA.f.y = clampa(ex2f(PA.f.y));
            alB.f.x = clampa(ex2f(PB.f.x));
            alB.f.y = clampa(ex2f(PB.f.y));
            const u64 wvA = fmul2(alA.u, trA);
            trA = ffma2(alA.u, m1, trA);
            const u64 wvB = fmul2(alB.u, trB);
            trB = ffma2(alB.u, m1, trB);
            aR0 = ffma2(wvA, crr, aR0);
            aG0 = ffma2(wvA, cgg, aG0);
            aB0 = ffma2(wvA, cbb, aB0);
            aR1 = ffma2(wvB, crr, aR1);
            aG1 = ffma2(wvB, cgg, aG1);
            aB1 = ffma2(wvB, cbb, aB1);
        }
    }

    // ---- epilogue: write 4 pixels ----
    const int gx = tx * 64 + lx;
    const int gy = ty * 64 + qtr * 16 + bl * 4;
    F2U R0, G0, B0, R1, G1, B1;
    R0.u = aR0; G0.u = aG0; B0.u = aB0;
    R1.u = aR1; G1.u = aG1; B1.u = aB1;
    float* o = out + ((size_t)gy * WIMG + gx) * 3;
    o[0] = R0.f.x; o[1] = G0.f.x; o[2] = B0.f.x;  o += WIMG * 3;
    o[0] = R0.f.y; o[1] = G0.f.y; o[2] = B0.f.y;  o += WIMG * 3;
    o[0] = R1.f.x; o[1] = G1.f.x; o[2] = B1.f.x;  o += WIMG * 3;
    o[0] = R1.f.y; o[1] = G1.f.y; o[2] = B1.f.y;
}

extern "C" void kernel_launch(void* const* d_in, const int* in_sizes, int n_in,
                              void* d_out, int out_size)
{
    const float* mu   = (const float*)d_in[0];
    const float* cov  = (const float*)d_in[1];
    const float* opac = (const float*)d_in[2];
    const float* col  = (const float*)d_in[3];
    const int*   tidx = (const int*)  d_in[4];
    float* out = (float*)d_out;

    // 64 tiles x 4 quarters = 256 CTAs, 256 threads, single launch
    fused_kernel<<<256, 256>>>(mu, cov, opac, col, tidx, out);
}